// round 11
// baseline (speedup 1.0000x reference)
#include <cuda_runtime.h>
#include <stdint.h>

#define DIM       300
#define VEC4      (DIM / 4)          // 75 float4 per row
#define VMAX      200000
#define KMAX      16
#define NBLOCKS   592                // 4 per SM (148 SMs), persistent
#define NTHREADS  256
#define WPB       (NTHREADS / 32)    // 8 warps per block
#define NWARPS    (NBLOCKS * WPB)    // 4736
#define ROWS_PER_ITER 4

// Device staging + scratch (no cudaMalloc; __device__ globals are sanctioned)
__device__ float    g_emb[(size_t)VMAX * DIM];   // staging for CE-copied rows
__device__ float    g_scores[VMAX];
__device__ unsigned g_done = 0;

__device__ __forceinline__ float dot4(float4 a, float4 b)
{
    return a.x * b.x + a.y * b.y + a.z * b.z + a.w * b.w;
}

// ---------------------------------------------------------------------------
// Warp-per-row dot products for rows [rlo, rhi) reading matrix `src`
// (either host-resident original or device staging). Query from `qsrc`.
// ---------------------------------------------------------------------------
__device__ __forceinline__ void dot_range(const float* __restrict__ src,
                                          const float* __restrict__ qsrc,
                                          int qrow, int rlo, int rhi)
{
    const int lane = threadIdx.x & 31;
    const int warp = blockIdx.x * WPB + (threadIdx.x >> 5);

    const float4 zero = make_float4(0.f, 0.f, 0.f, 0.f);
    const bool   t2   = (lane + 64) < VEC4;     // lanes 0..10 do the 3rd quarter

    const float4* __restrict__ wp =
        reinterpret_cast<const float4*>(qsrc + (size_t)qrow * DIM);
    const float4 b0 = __ldg(wp + lane);
    const float4 b1 = __ldg(wp + lane + 32);
    const float4 b2 = t2 ? __ldg(wp + lane + 64) : zero;

    const int n = rhi - rlo;
    for (int base = warp; base < n; base += ROWS_PER_ITER * NWARPS) {
        float4 a[ROWS_PER_ITER][3];
        int    rr[ROWS_PER_ITER];
        bool   hv[ROWS_PER_ITER];

        #pragma unroll
        for (int j = 0; j < ROWS_PER_ITER; j++) {
            rr[j] = base + j * NWARPS;
            hv[j] = rr[j] < n;
            const int safe = hv[j] ? (rlo + rr[j]) : rlo;
            const float4* __restrict__ rp =
                reinterpret_cast<const float4*>(src + (size_t)safe * DIM);
            a[j][0] = __ldg(rp + lane);
            a[j][1] = __ldg(rp + lane + 32);
            a[j][2] = t2 ? __ldg(rp + lane + 64) : zero;
        }

        #pragma unroll
        for (int j = 0; j < ROWS_PER_ITER; j++) {
            float s = dot4(a[j][0], b0) + dot4(a[j][1], b1) + dot4(a[j][2], b2);
            #pragma unroll
            for (int off = 16; off; off >>= 1)
                s += __shfl_xor_sync(0xFFFFFFFFu, s, off);
            if (lane == 0 && hv[j])
                g_scores[rlo + rr[j]] = s;
        }
    }
}

// ---------------------------------------------------------------------------
// Kernel 1: rows [H, V) directly from the host-resident source (C2C via LDG),
// running CONCURRENTLY with the CE copy of rows [0, H) into g_emb.
// ---------------------------------------------------------------------------
__global__ __launch_bounds__(NTHREADS) void dot_direct_kernel(const int* __restrict__ wordid,
                                                              const float* __restrict__ emb,
                                                              int H, int V)
{
    dot_range(emb, emb, __ldg(wordid), H, V);
}

// ---------------------------------------------------------------------------
// Kernel 2 (after join): rows [0, H) from device staging (local DRAM, cheap),
// then last-block top-K over all V scores.
// ---------------------------------------------------------------------------
__global__ __launch_bounds__(NTHREADS) void dot_staged_topk_kernel(const int* __restrict__ wordid,
                                                                   const float* __restrict__ emb,
                                                                   const int* __restrict__ topk_p,
                                                                   float* __restrict__ out,
                                                                   int out_size,
                                                                   int H, int V)
{
    dot_range(g_emb, emb, __ldg(wordid), 0, H);

    // ---- last-block-done handoff ----
    __shared__ bool isLast;
    __threadfence();
    if (threadIdx.x == 0) {
        unsigned prev = atomicAdd(&g_done, 1u);
        isLast = (prev == (unsigned)(gridDim.x - 1));
    }
    __syncthreads();
    if (!isLast) return;
    __threadfence();   // acquire: all blocks' score stores visible

    // ---- top-K over g_scores ----
    int K = *topk_p + 1;
    if (K > KMAX) K = KMAX;
    if (K < 1)    K = 1;

    __shared__ float svals[NTHREADS * KMAX];
    __shared__ int   sids [NTHREADS * KMAX];

    float lv[KMAX];
    int   li[KMAX];
    #pragma unroll
    for (int i = 0; i < KMAX; i++) { lv[i] = -3.0e38f; li[i] = 0x7FFFFFFF; }
    float kmin = -3.0e38f;

    const int t = threadIdx.x;
    for (int r = t; r < V; r += NTHREADS) {
        float v = g_scores[r];
        if (v > kmin) {
            int pos = K - 1;
            while (pos > 0 && lv[pos - 1] < v) {
                lv[pos] = lv[pos - 1];
                li[pos] = li[pos - 1];
                pos--;
            }
            lv[pos] = v;
            li[pos] = r;
            kmin = lv[K - 1];
        }
    }

    for (int i = 0; i < K; i++) {
        svals[t * KMAX + i] = lv[i];
        sids [t * KMAX + i] = li[i];
    }
    __syncthreads();

    if (t == 0) {
        float fv[KMAX];
        int   fi[KMAX];
        #pragma unroll
        for (int i = 0; i < KMAX; i++) { fv[i] = -3.0e38f; fi[i] = 0x7FFFFFFF; }
        float fmin = -3.0e38f;

        for (int tt = 0; tt < NTHREADS; tt++) {
            for (int kk = 0; kk < K; kk++) {
                float v  = svals[tt * KMAX + kk];
                int   id = sids [tt * KMAX + kk];
                if (id == 0x7FFFFFFF) break;
                bool better = (v > fmin) || (v == fmin && id < fi[K - 1]);
                if (better) {
                    int pos = K - 1;
                    while (pos > 0 &&
                           (fv[pos - 1] < v ||
                            (fv[pos - 1] == v && fi[pos - 1] > id))) {
                        fv[pos] = fv[pos - 1];
                        fi[pos] = fi[pos - 1];
                        pos--;
                    }
                    fv[pos] = v;
                    fi[pos] = id;
                    fmin = fv[K - 1];
                }
            }
        }

        for (int i = 0; i < K && i < out_size; i++)
            out[i] = fv[i];
        if (out_size >= 2 * K) {
            for (int i = 0; i < K; i++)
                out[K + i] = (float)fi[i];
        }

        g_done = 0;   // reset for next (deterministic) replay
    }
}

// ---------------------------------------------------------------------------
extern "C" void kernel_launch(void* const* d_in, const int* in_sizes, int n_in,
                              void* d_out, int out_size)
{
    const int*   wordid = (const int*)  d_in[0];
    const float* emb    = (const float*)d_in[1];
    const int*   topk   = (const int*)  d_in[2];
    float*       out    = (float*)      d_out;

    const int V = in_sizes[1] / DIM;   // 200000

    // CE fraction: f = 174 / (174 + 290) ≈ 0.375 of bytes go via copy engine
    const int H = (int)(((long long)V * 3) / 8);   // staged rows [0, H)

    static float*       emb_dev = nullptr;
    static cudaStream_t s2      = nullptr;
    static cudaEvent_t  evFork  = nullptr, evJoin = nullptr;
    if (!emb_dev) {
        cudaGetSymbolAddress((void**)&emb_dev, g_emb);
        cudaStreamCreateWithFlags(&s2, cudaStreamNonBlocking);
        cudaEventCreateWithFlags(&evFork, cudaEventDisableTiming);
        cudaEventCreateWithFlags(&evJoin, cudaEventDisableTiming);
    }

    // Fork: CE copies rows [0,H) on s2 while kernel 1 reads [H,V) from host.
    cudaEventRecord(evFork, 0);
    cudaStreamWaitEvent(s2, evFork, 0);
    cudaMemcpyAsync(emb_dev, emb, (size_t)H * DIM * sizeof(float),
                    cudaMemcpyDefault, s2);
    cudaEventRecord(evJoin, s2);

    dot_direct_kernel<<<NBLOCKS, NTHREADS>>>(wordid, emb, H, V);

    // Join: kernel 2 needs both the staged copy and kernel 1's scores.
    cudaStreamWaitEvent(0, evJoin, 0);
    dot_staged_topk_kernel<<<NBLOCKS, NTHREADS>>>(wordid, emb, topk,
                                                  out, out_size, H, V);
}

// round 12
// speedup vs baseline: 1.1329x; 1.1329x over previous
#include <cuda_runtime.h>
#include <stdint.h>

#define DIM        300
#define ROW_BYTES  (DIM * 4)            // 1200 (multiple of 16)
#define VEC4       (DIM / 4)            // 75 float4 per row
#define VMAX       200000
#define KMAX       16
#define NTHREADS   512
#define WPB        (NTHREADS / 32)      // 16 warps
#define TILE_ROWS  32
#define TILE_BYTES (TILE_ROWS * ROW_BYTES)   // 38400
#define STAGES     5
#define NBLOCKS    148                  // 1 persistent block per SM
#define SMEM_DATA  1024                 // data region offset (barriers below)
#define SMEM_TOTAL (SMEM_DATA + STAGES * TILE_BYTES)   // 193024 B

// Scratch (no cudaMalloc; __device__ globals are the sanctioned path)
__device__ float    g_scores[VMAX];
__device__ unsigned g_done = 0;

// ---------------------------------------------------------------------------
// PTX helpers
// ---------------------------------------------------------------------------
__device__ __forceinline__ uint32_t smem_u32(const void* p)
{
    uint32_t a;
    asm("{ .reg .u64 t; cvta.to.shared.u64 t, %1; cvt.u32.u64 %0, t; }"
        : "=r"(a) : "l"(p));
    return a;
}
__device__ __forceinline__ void mbar_init(uint32_t mbar, uint32_t count)
{
    asm volatile("mbarrier.init.shared.b64 [%0], %1;" :: "r"(mbar), "r"(count) : "memory");
}
__device__ __forceinline__ void mbar_expect_tx(uint32_t mbar, uint32_t bytes)
{
    asm volatile("mbarrier.arrive.expect_tx.shared.b64 _, [%0], %1;"
                 :: "r"(mbar), "r"(bytes) : "memory");
}
__device__ __forceinline__ void mbar_wait(uint32_t mbar, uint32_t parity)
{
    uint32_t done;
    asm volatile(
        "{\n\t.reg .pred p;\n\t"
        "mbarrier.try_wait.parity.acquire.cta.shared::cta.b64 p, [%1], %2;\n\t"
        "selp.b32 %0, 1, 0, p;\n\t}"
        : "=r"(done) : "r"(mbar), "r"(parity) : "memory");
    if (!done) {
        asm volatile(
            "{\n\t.reg .pred P1;\n\t"
            "WL_%=:\n\t"
            "mbarrier.try_wait.parity.acquire.cta.shared::cta.b64 P1, [%0], %1, 0x989680;\n\t"
            "@P1 bra.uni WD_%=;\n\t"
            "bra.uni WL_%=;\n\t"
            "WD_%=:\n\t}"
            :: "r"(mbar), "r"(parity) : "memory");
    }
}
// Bulk async copy global -> shared (UBLKCP). Burst reads over C2C.
__device__ __forceinline__ void bulk_g2s(uint32_t dst_smem, const void* src,
                                         uint32_t bytes, uint32_t mbar)
{
    asm volatile(
        "cp.async.bulk.shared::cluster.global.mbarrier::complete_tx::bytes "
        "[%0], [%1], %2, [%3];"
        :: "r"(dst_smem), "l"(src), "r"(bytes), "r"(mbar) : "memory");
}

__device__ __forceinline__ float dot4(float4 a, float4 b)
{
    return a.x * b.x + a.y * b.y + a.z * b.z + a.w * b.w;
}
__device__ __forceinline__ float4 lds128(uint32_t addr)
{
    float4 v;
    asm volatile("ld.shared.v4.f32 {%0,%1,%2,%3}, [%4];"
                 : "=f"(v.x), "=f"(v.y), "=f"(v.z), "=f"(v.w) : "r"(addr));
    return v;
}

// ---------------------------------------------------------------------------
// Fused kernel: bulk-copy pipeline (host C2C -> SMEM) + dots + last-block topK
// ---------------------------------------------------------------------------
__global__ __launch_bounds__(NTHREADS) void fused_kernel(const int* __restrict__ wordid,
                                                         const float* __restrict__ emb,
                                                         const int* __restrict__ topk_p,
                                                         float* __restrict__ out,
                                                         int out_size,
                                                         int V)
{
    extern __shared__ char smem[];
    const uint32_t sb   = smem_u32(smem);
    const int      tid  = threadIdx.x;
    const int      lane = tid & 31;
    const int      wid  = tid >> 5;

    // this block's contiguous row range
    const int chunk = (V + gridDim.x - 1) / gridDim.x;
    const int r0    = blockIdx.x * chunk;
    const int r1    = (r0 + chunk < V) ? (r0 + chunk) : V;
    const int nrows = r1 - r0;
    const int ntile = (nrows + TILE_ROWS - 1) / TILE_ROWS;

    if (tid == 0)
        for (int s = 0; s < STAGES; s++)
            mbar_init(sb + s * 8, 1);
    __syncthreads();

    // query vector in registers (host lines, L1-cached, shared by all blocks)
    const float4 zero = make_float4(0.f, 0.f, 0.f, 0.f);
    const bool   t2   = (lane + 64) < VEC4;          // lanes 0..10
    const int    w    = __ldg(wordid);
    const float4* __restrict__ wp =
        reinterpret_cast<const float4*>(emb + (size_t)w * DIM);
    const float4 b0 = __ldg(wp + lane);
    const float4 b1 = __ldg(wp + lane + 32);
    const float4 b2 = t2 ? __ldg(wp + lane + 64) : zero;

    // prologue: fill all stages
    if (tid == 0) {
        const int pre = (ntile < STAGES) ? ntile : STAGES;
        for (int s = 0; s < pre; s++) {
            const int tr   = r0 + s * TILE_ROWS;
            const int rows = (r1 - tr < TILE_ROWS) ? (r1 - tr) : TILE_ROWS;
            const uint32_t bytes = (uint32_t)rows * ROW_BYTES;
            mbar_expect_tx(sb + s * 8, bytes);
            bulk_g2s(sb + SMEM_DATA + s * TILE_BYTES,
                     emb + (size_t)tr * DIM, bytes, sb + s * 8);
        }
    }

    // mainloop
    for (int i = 0; i < ntile; i++) {
        const int      buf = i % STAGES;
        const uint32_t mb  = sb + buf * 8;
        mbar_wait(mb, (i / STAGES) & 1);

        const int tr   = r0 + i * TILE_ROWS;
        const int rows = (r1 - tr < TILE_ROWS) ? (r1 - tr) : TILE_ROWS;

        for (int rl = wid; rl < rows; rl += WPB) {
            const uint32_t base = sb + SMEM_DATA + buf * TILE_BYTES + rl * ROW_BYTES;
            const float4 a0 = lds128(base + lane * 16);
            const float4 a1 = lds128(base + 512 + lane * 16);
            const float4 a2 = t2 ? lds128(base + 1024 + lane * 16) : zero;

            float s = dot4(a0, b0) + dot4(a1, b1) + dot4(a2, b2);
            #pragma unroll
            for (int off = 16; off; off >>= 1)
                s += __shfl_xor_sync(0xFFFFFFFFu, s, off);
            if (lane == 0)
                g_scores[tr + rl] = s;
        }
        __syncthreads();   // whole block done reading buf -> safe to refill

        const int nx = i + STAGES;
        if (tid == 0 && nx < ntile) {
            const int tr2   = r0 + nx * TILE_ROWS;
            const int rows2 = (r1 - tr2 < TILE_ROWS) ? (r1 - tr2) : TILE_ROWS;
            const uint32_t bytes = (uint32_t)rows2 * ROW_BYTES;
            mbar_expect_tx(mb, bytes);
            bulk_g2s(sb + SMEM_DATA + buf * TILE_BYTES,
                     emb + (size_t)tr2 * DIM, bytes, mb);
        }
    }

    // ---- last-block-done handoff ----
    __shared__ bool isLast;
    __threadfence();
    if (tid == 0) {
        unsigned prev = atomicAdd(&g_done, 1u);
        isLast = (prev == (unsigned)(gridDim.x - 1));
    }
    __syncthreads();
    if (!isLast) return;
    __threadfence();   // acquire: all blocks' score stores visible

    // ---- phase 2: top-K over g_scores (reuse dynamic SMEM for candidates) ----
    int K = *topk_p + 1;
    if (K > KMAX) K = KMAX;
    if (K < 1)    K = 1;

    float* svals = reinterpret_cast<float*>(smem + SMEM_DATA);                       // 32 KB
    int*   sids  = reinterpret_cast<int*>  (smem + SMEM_DATA + NTHREADS * KMAX * 4); // 32 KB

    float lv[KMAX];
    int   li[KMAX];
    #pragma unroll
    for (int i = 0; i < KMAX; i++) { lv[i] = -3.0e38f; li[i] = 0x7FFFFFFF; }
    float kmin = -3.0e38f;

    for (int r = tid; r < V; r += NTHREADS) {
        float v = g_scores[r];
        if (v > kmin) {
            int pos = K - 1;
            while (pos > 0 && lv[pos - 1] < v) {
                lv[pos] = lv[pos - 1];
                li[pos] = li[pos - 1];
                pos--;
            }
            lv[pos] = v;
            li[pos] = r;
            kmin = lv[K - 1];
        }
    }

    for (int i = 0; i < K; i++) {
        svals[tid * KMAX + i] = lv[i];
        sids [tid * KMAX + i] = li[i];
    }
    __syncthreads();

    if (tid == 0) {
        float fv[KMAX];
        int   fi[KMAX];
        #pragma unroll
        for (int i = 0; i < KMAX; i++) { fv[i] = -3.0e38f; fi[i] = 0x7FFFFFFF; }
        float fmin = -3.0e38f;

        for (int tt = 0; tt < NTHREADS; tt++) {
            for (int kk = 0; kk < K; kk++) {
                float v  = svals[tt * KMAX + kk];
                int   id = sids [tt * KMAX + kk];
                if (id == 0x7FFFFFFF) break;
                bool better = (v > fmin) || (v == fmin && id < fi[K - 1]);
                if (better) {
                    int pos = K - 1;
                    while (pos > 0 &&
                           (fv[pos - 1] < v ||
                            (fv[pos - 1] == v && fi[pos - 1] > id))) {
                        fv[pos] = fv[pos - 1];
                        fi[pos] = fi[pos - 1];
                        pos--;
                    }
                    fv[pos] = v;
                    fi[pos] = id;
                    fmin = fv[K - 1];
                }
            }
        }

        for (int i = 0; i < K && i < out_size; i++)
            out[i] = fv[i];
        if (out_size >= 2 * K) {
            for (int i = 0; i < K; i++)
                out[K + i] = (float)fi[i];
        }

        g_done = 0;   // reset for next (deterministic) replay
    }
}

// ---------------------------------------------------------------------------
extern "C" void kernel_launch(void* const* d_in, const int* in_sizes, int n_in,
                              void* d_out, int out_size)
{
    const int*   wordid = (const int*)  d_in[0];
    const float* emb    = (const float*)d_in[1];
    const int*   topk   = (const int*)  d_in[2];
    float*       out    = (float*)      d_out;

    const int V = in_sizes[1] / DIM;   // 200000

    static bool attr_set = false;
    if (!attr_set) {
        cudaFuncSetAttribute(fused_kernel,
                             cudaFuncAttributeMaxDynamicSharedMemorySize,
                             SMEM_TOTAL);
        attr_set = true;
    }

    fused_kernel<<<NBLOCKS, NTHREADS, SMEM_TOTAL>>>(wordid, emb, topk,
                                                    out, out_size, V);
}

// round 13
// speedup vs baseline: 1.7316x; 1.5285x over previous
#include <cuda_runtime.h>
#include <stdint.h>

#define DIM       300
#define VEC4      (DIM / 4)          // 75 float4 per row
#define VMAX      200000
#define KMAX      16
#define NBLOCKS   592                // 4 per SM (148 SMs)
#define NTHREADS  256
#define WPB       (NTHREADS / 32)    // 8 warps per block
#define NWARPS    (NBLOCKS * WPB)    // 4736
#define ROWS_PER_ITER 4
#define H_RES     80000              // rows kept L2-resident (96 MB of 126 MB L2)

// Scratch (no cudaMalloc allowed; __device__ globals are the sanctioned path)
__device__ float    g_scores[VMAX];
__device__ unsigned g_done = 0;

__device__ __forceinline__ float dot4(float4 a, float4 b)
{
    return a.x * b.x + a.y * b.y + a.z * b.z + a.w * b.w;
}

// ld.global.nc.v4 with an L2 cache-eviction policy attached
__device__ __forceinline__ float4 ldg_pol(const float4* __restrict__ p, uint64_t pol)
{
    float4 v;
    asm volatile("ld.global.nc.L2::cache_hint.v4.f32 {%0,%1,%2,%3}, [%4], %5;"
                 : "=f"(v.x), "=f"(v.y), "=f"(v.z), "=f"(v.w)
                 : "l"(p), "l"(pol));
    return v;
}

// ---------------------------------------------------------------------------
// Fused kernel (R10 transport + L2 residency policies):
//   rows [0, H)  : evict_last  -> stay warm in L2 across graph replays
//   rows [H, V)  : evict_first -> stream through L2 without evicting the
//                                 resident set
//   Phase 2 (last block): top-K over g_scores, write out.
// ---------------------------------------------------------------------------
__global__ __launch_bounds__(NTHREADS) void fused_kernel(const int* __restrict__ wordid,
                                                         const float* __restrict__ emb,
                                                         const int* __restrict__ topk_p,
                                                         float* __restrict__ out,
                                                         int out_size,
                                                         int V,
                                                         int H)
{
    const int lane = threadIdx.x & 31;
    const int warp = blockIdx.x * WPB + (threadIdx.x >> 5);

    uint64_t pol_last, pol_first;
    asm("createpolicy.fractional.L2::evict_last.b64  %0, 1.0;" : "=l"(pol_last));
    asm("createpolicy.fractional.L2::evict_first.b64 %0, 1.0;" : "=l"(pol_first));

    const float4 zero = make_float4(0.f, 0.f, 0.f, 0.f);
    const bool   t2   = (lane + 64) < VEC4;     // lanes 0..10 do the 3rd load

    // ---- query vector in registers (resident policy; hot every replay) ----
    const int w = __ldg(wordid);
    const float4* __restrict__ wp =
        reinterpret_cast<const float4*>(emb + (size_t)w * DIM);
    const float4 b0 = ldg_pol(wp + lane,      pol_last);
    const float4 b1 = ldg_pol(wp + lane + 32, pol_last);
    const float4 b2 = t2 ? ldg_pol(wp + lane + 64, pol_last) : zero;

    // ---- phase 1: 4 rows per iteration, all 12 loads issued before use ----
    for (int base = warp; base < V; base += ROWS_PER_ITER * NWARPS) {
        float4   a[ROWS_PER_ITER][3];
        int      rr[ROWS_PER_ITER];
        bool     hv[ROWS_PER_ITER];

        #pragma unroll
        for (int j = 0; j < ROWS_PER_ITER; j++) {
            rr[j] = base + j * NWARPS;
            hv[j] = rr[j] < V;
            const int safe = hv[j] ? rr[j] : 0;
            const uint64_t pol = (safe < H) ? pol_last : pol_first;
            const float4* __restrict__ rp =
                reinterpret_cast<const float4*>(emb + (size_t)safe * DIM);
            a[j][0] = ldg_pol(rp + lane,      pol);
            a[j][1] = ldg_pol(rp + lane + 32, pol);
            a[j][2] = t2 ? ldg_pol(rp + lane + 64, pol) : zero;
        }

        #pragma unroll
        for (int j = 0; j < ROWS_PER_ITER; j++) {
            float s = dot4(a[j][0], b0) + dot4(a[j][1], b1) + dot4(a[j][2], b2);
            #pragma unroll
            for (int off = 16; off; off >>= 1)
                s += __shfl_xor_sync(0xFFFFFFFFu, s, off);
            if (lane == 0 && hv[j])
                g_scores[rr[j]] = s;
        }
    }

    // ---- last-block-done handoff ----
    __shared__ bool isLast;
    __threadfence();
    if (threadIdx.x == 0) {
        unsigned prev = atomicAdd(&g_done, 1u);
        isLast = (prev == (unsigned)(gridDim.x - 1));
    }
    __syncthreads();
    if (!isLast) return;
    __threadfence();   // acquire: all blocks' score stores visible

    // ---- phase 2: top-K over g_scores ----
    int K = *topk_p + 1;
    if (K > KMAX) K = KMAX;
    if (K < 1)    K = 1;

    __shared__ float svals[NTHREADS * KMAX];
    __shared__ int   sids [NTHREADS * KMAX];

    float lv[KMAX];
    int   li[KMAX];
    #pragma unroll
    for (int i = 0; i < KMAX; i++) { lv[i] = -3.0e38f; li[i] = 0x7FFFFFFF; }
    float kmin = -3.0e38f;

    const int t = threadIdx.x;
    for (int r = t; r < V; r += NTHREADS) {
        float v = g_scores[r];
        if (v > kmin) {
            int pos = K - 1;
            while (pos > 0 && lv[pos - 1] < v) {
                lv[pos] = lv[pos - 1];
                li[pos] = li[pos - 1];
                pos--;
            }
            lv[pos] = v;
            li[pos] = r;
            kmin = lv[K - 1];
        }
    }

    for (int i = 0; i < K; i++) {
        svals[t * KMAX + i] = lv[i];
        sids [t * KMAX + i] = li[i];
    }
    __syncthreads();

    if (t == 0) {
        float fv[KMAX];
        int   fi[KMAX];
        #pragma unroll
        for (int i = 0; i < KMAX; i++) { fv[i] = -3.0e38f; fi[i] = 0x7FFFFFFF; }
        float fmin = -3.0e38f;

        for (int tt = 0; tt < NTHREADS; tt++) {
            for (int kk = 0; kk < K; kk++) {
                float v  = svals[tt * KMAX + kk];
                int   id = sids [tt * KMAX + kk];
                if (id == 0x7FFFFFFF) break;
                bool better = (v > fmin) || (v == fmin && id < fi[K - 1]);
                if (better) {
                    int pos = K - 1;
                    while (pos > 0 &&
                           (fv[pos - 1] < v ||
                            (fv[pos - 1] == v && fi[pos - 1] > id))) {
                        fv[pos] = fv[pos - 1];
                        fi[pos] = fi[pos - 1];
                        pos--;
                    }
                    fv[pos] = v;
                    fi[pos] = id;
                    fmin = fv[K - 1];
                }
            }
        }

        for (int i = 0; i < K && i < out_size; i++)
            out[i] = fv[i];
        if (out_size >= 2 * K) {
            for (int i = 0; i < K; i++)
                out[K + i] = (float)fi[i];
        }

        g_done = 0;   // reset for next (deterministic) replay
    }
}

// ---------------------------------------------------------------------------
extern "C" void kernel_launch(void* const* d_in, const int* in_sizes, int n_in,
                              void* d_out, int out_size)
{
    const int*   wordid = (const int*)  d_in[0];
    const float* emb    = (const float*)d_in[1];
    const int*   topk   = (const int*)  d_in[2];
    float*       out    = (float*)      d_out;

    const int V = in_sizes[1] / DIM;   // 200000
    int H = H_RES;
    if (H > V) H = V;

    fused_kernel<<<NBLOCKS, NTHREADS>>>(wordid, emb, topk, out, out_size, V, H);
}